// round 13
// baseline (speedup 1.0000x reference)
#include <cuda_runtime.h>
#include <cuda_fp16.h>
#include <cstdint>

#define DI __device__ __forceinline__

constexpr int T  = 15;
constexpr int NT = 512;      // 16 warps: 4 groups x 4 warps
constexpr int MR = 64;       // batch rows per CTA (16 per group)

// ---------------- SMEM byte offsets ----------------
// Weight tiles: [256 n'][64 k] fp16, 128B rows, SW128 xor swizzle (32768 B each)
constexpr int O_W0   = 0;         // Whh0 (fp16)
constexpr int O_W1I  = 32768;     // Wih1
constexpr int O_W1H  = 65536;     // Whh1
// h-state tiles: [64 rows][64 k] fp16 SW128 (8192 B each)
constexpr int O_H0   = 98304;
constexpr int O_H1   = 106496;
constexpr int O_BIAS1 = 114688;   // 64 x float4 (i,f,g,o)
constexpr int O_FCW   = 115712;   // 64 floats
constexpr int O_SRED  = 115968;   // 64 rows x 4 floats
constexpr int O_ZP    = 116992;   // zp: [64 rows][256 n'] fp32, row-xor swizzled (64KB)
constexpr int SMEM_TOTAL = 182528;

DI uint32_t smem_u32(const void* p) {
    uint32_t a;
    asm("{ .reg .u64 t; cvta.to.shared.u64 t, %1; cvt.u32.u64 %0, t; }" : "=r"(a) : "l"(p));
    return a;
}
DI void sts16(uint32_t addr, unsigned short u) {
    asm volatile("st.shared.b16 [%0], %1;" :: "r"(addr), "h"(u) : "memory");
}
DI void sts32(uint32_t addr, float v) {
    asm volatile("st.shared.f32 [%0], %1;" :: "r"(addr), "f"(v) : "memory");
}
DI float2 lds64(uint32_t addr) {
    float2 v;
    asm("ld.shared.v2.f32 {%0,%1}, [%2];" : "=f"(v.x), "=f"(v.y) : "r"(addr));
    return v;
}
DI void ldsm4(uint32_t* r, uint32_t addr) {
    asm volatile("ldmatrix.sync.aligned.m8n8.x4.shared.b16 {%0,%1,%2,%3}, [%4];"
                 : "=r"(r[0]), "=r"(r[1]), "=r"(r[2]), "=r"(r[3]) : "r"(addr));
}
DI void mma4(float* d, const uint32_t* a, uint32_t b0, uint32_t b1, const float* c) {
    asm("mma.sync.aligned.m16n8k16.row.col.f32.f16.f16.f32 "
        "{%0,%1,%2,%3},{%4,%5,%6,%7},{%8,%9},{%10,%11,%12,%13};"
        : "=f"(d[0]), "=f"(d[1]), "=f"(d[2]), "=f"(d[3])
        : "r"(a[0]), "r"(a[1]), "r"(a[2]), "r"(a[3]), "r"(b0), "r"(b1),
          "f"(c[0]), "f"(c[1]), "f"(c[2]), "f"(c[3]));
}
// named barrier: per-group sync (128 threads), with memory ordering
DI void bar_grp(int id) {
    asm volatile("bar.sync %0, 128;" :: "r"(id) : "memory");
}

// swizzled offset inside a [n'][64k] fp16 tile with 128B rows
DI uint32_t swoff(int np, int k) {
    return (uint32_t)(np * 128 + k * 2) ^ (uint32_t)((np & 7) << 4);
}

// ---- fast activations: single MUFU.TANH each ----
DI float tanh_(float x) {
    float r;
    asm("tanh.approx.f32 %0, %1;" : "=f"(r) : "f"(x));
    return r;
}
DI float sigf(float x) {                 // 0.5*tanh(x/2) + 0.5
    return fmaf(tanh_(0.5f * x), 0.5f, 0.5f);
}

// 1-term fp16 GEMM, accumulate into D[32]:
// D += A*W over K=64; warp n-range = 64 (4 chunks of 16)
DI void gemm1acc(float* D, uint32_t aH, uint32_t bW,
                 uint32_t akl, uint32_t axm, uint32_t bkl, uint32_t bxm)
{
    #pragma unroll
    for (int ks = 0; ks < 4; ks++) {
        const uint32_t kA = ((uint32_t)(ks * 32) + akl) ^ axm;
        const uint32_t kB = ((uint32_t)(ks * 32) + bkl) ^ bxm;
        uint32_t ah[4];
        ldsm4(ah, aH + kA);
        #pragma unroll
        for (int p = 0; p < 4; p++) {
            uint32_t bh[4];
            ldsm4(bh, bW + p * 2048 + kB);
            float* d0 = D + p * 8;
            mma4(d0,     ah, bh[0], bh[1], d0);
            mma4(d0 + 4, ah, bh[2], bh[3], d0 + 4);
        }
    }
}

// epilogue: gate exchange, LSTM cell update, h writeback (fp16). LAYER 1 adds
// bias (layer-0 bias folded into zp) and accumulates the fc dot product.
template<int LAYER>
DI float epilogue(float* D, float* cs, int odd, int jconst,
                  uint32_t eH, uint32_t exm,
                  const float4* sBias1, const float* sFcw)
{
    float fcacc = 0.0f;
    #pragma unroll
    for (int p = 0; p < 4; p++) {
        #pragma unroll
        for (int q = 0; q < 2; q++) {
            const int di = p * 8 + q * 4;
            float x0 = D[di], x1 = D[di + 1], x2 = D[di + 2], x3 = D[di + 3];
            float e1 = __shfl_xor_sync(0xffffffffu, odd ? x0 : x2, 1);
            float e2 = __shfl_xor_sync(0xffffffffu, odd ? x1 : x3, 1);
            float gi = odd ? e1 : x0;
            float gf = odd ? e2 : x1;
            float gg = odd ? x2 : e1;
            float go = odd ? x3 : e2;
            const int j = jconst + p * 4 + q * 2;
            if (LAYER == 1) {
                const float4 b = sBias1[j];
                gi += b.x; gf += b.y; gg += b.z; go += b.w;
            }
            const float i_ = sigf(gi);
            const float f_ = sigf(gf);
            const float g_ = tanh_(gg);
            const float o_ = sigf(go);
            const int ci = p * 2 + q;
            const float cn = fmaf(f_, cs[ci], i_ * g_);
            cs[ci] = cn;
            const float h = o_ * tanh_(cn);
            if (LAYER == 1) fcacc = fmaf(h, sFcw[j], fcacc);
            const uint32_t co = ((uint32_t)(j * 2)) ^ exm;
            sts16(eH + co, __half_as_ushort(__float2half_rn(h)));
        }
    }
    return fcacc;
}

// ===========================================================================
__global__ void __launch_bounds__(NT, 1) lstm_hmma_kernel(
    const float* __restrict__ z,
    const float* __restrict__ Wih0, const float* __restrict__ Whh0,
    const float* __restrict__ bih0, const float* __restrict__ bhh0,
    const float* __restrict__ Wih1, const float* __restrict__ Whh1,
    const float* __restrict__ bih1, const float* __restrict__ bhh1,
    const float* __restrict__ Wfc,  const float* __restrict__ bfc,
    float* __restrict__ out)
{
    extern __shared__ char sm[];
    const uint32_t smb = smem_u32(sm);
    const int tid  = threadIdx.x;
    const int lane = tid & 31;
    const int w    = tid >> 5;
    const int grp  = w >> 2;       // row group: rows grp*16 .. +15
    const int ng   = w & 3;        // n-quarter: n' in [ng*64, ng*64+64)
    const int bid  = grp + 1;      // named barrier id

    // ---- ldmatrix lane addressing constants ----
    const int j8  = lane & 7;
    const int sel = lane >> 3;
    const int arow = grp * 16 + j8 + (sel & 1) * 8;     // local A row this lane feeds
    const uint32_t axm = (uint32_t)j8 << 4;             // arow & 7 == j8
    const uint32_t akl = (uint32_t)(sel >> 1) << 4;
    const int bnl = (sel >> 1) * 8 + j8;                // B row within 16-row chunk
    const uint32_t bxm = (uint32_t)j8 << 4;
    const uint32_t bkl = (uint32_t)(sel & 1) << 4;

    const uint32_t aOff = (uint32_t)arow * 128;
    const uint32_t bOff = (uint32_t)(ng * 64 + bnl) * 128;
    const uint32_t aH0 = smb + O_H0 + aOff;
    const uint32_t aH1 = smb + O_H1 + aOff;
    const uint32_t bW0  = smb + O_W0 + bOff;
    const uint32_t bW1I = smb + O_W1I + bOff;
    const uint32_t bW1H = smb + O_W1H + bOff;

    // ---- epilogue lane constants ----
    const int gid = lane >> 2, tig = lane & 3;
    const int odd = tig & 1;
    const int erow = grp * 16 + gid + 8 * odd;          // local row this lane updates
    const uint32_t eOff = (uint32_t)erow * 128;
    const uint32_t exm  = (uint32_t)(erow & 7) << 4;
    const uint32_t eH0 = smb + O_H0 + eOff;
    const uint32_t eH1 = smb + O_H1 + eOff;
    const int jconst = ng * 16 + (tig >> 1);

    // ---- zp SMEM addressing (row-xor swizzle: ≤2-way conflicts) ----
    const int zr0 = grp * 16 + gid;                     // local rows zr0, zr0+8
    const uint32_t zxm = (uint32_t)((zr0 & 7) << 5);
    const uint32_t zpA = smb + O_ZP + (uint32_t)zr0 * 1024;
    const uint32_t zpB = zpA + 8 * 1024;

    float4* sBias1 = (float4*)(sm + O_BIAS1);
    float*  sFcw   = (float*)(sm + O_FCW);
    float*  sRed   = (float*)(sm + O_SRED);

    // ======== init: repack weights (fp16, gate-interleaved n'=4j+g) ========
    for (int idx = tid; idx < 16384; idx += NT) {
        const int r = idx >> 6, k = idx & 63;
        const int g = r >> 6, j = r & 63;
        const uint32_t off = swoff(j * 4 + g, k);
        *(__half*)(sm + O_W0  + off) = __float2half_rn(Whh0[idx]);
        *(__half*)(sm + O_W1I + off) = __float2half_rn(Wih1[idx]);
        *(__half*)(sm + O_W1H + off) = __float2half_rn(Whh1[idx]);
    }
    // stage Wih0 (fp32) in the h-tile area (16KB) + bias0 sums in SRED (1KB)
    float* sWz = (float*)(sm + O_H0);      // [256][16] fp32 (spans H0+H1)
    float* sB0 = (float*)(sm + O_SRED);    // [256]
    for (int idx = tid; idx < 4096; idx += NT) sWz[idx] = Wih0[idx];
    for (int idx = tid; idx < 256;  idx += NT) sB0[idx] = bih0[idx] + bhh0[idx];
    if (tid < 64) {
        sBias1[tid] = make_float4(bih1[tid] + bhh1[tid],
                                  bih1[64 + tid] + bhh1[64 + tid],
                                  bih1[128 + tid] + bhh1[128 + tid],
                                  bih1[192 + tid] + bhh1[192 + tid]);
        sFcw[tid] = Wfc[tid];
    }
    const float bfc_v = __ldg(bfc);
    __syncthreads();

    // ======== one-time exact z-projection + bias0 -> zp SMEM ========
    const int gbase = blockIdx.x * MR;
    {
        float zv0[16], zv1[16];
        const int r0 = gbase + grp * 16 + gid;
        #pragma unroll
        for (int k = 0; k < 16; k++) {
            zv0[k] = z[(size_t)r0 * 16 + k];
            zv1[k] = z[(size_t)(r0 + 8) * 16 + k];
        }
        #pragma unroll
        for (int p = 0; p < 4; p++) {
            #pragma unroll
            for (int q = 0; q < 2; q++) {
                #pragma unroll
                for (int e = 0; e < 2; e++) {
                    const int np = ng * 64 + p * 16 + q * 8 + tig * 2 + e;
                    const int orig = (np & 3) * 64 + (np >> 2);
                    const float* wr = sWz + orig * 16;
                    float s0 = sB0[orig], s1 = s0;
                    #pragma unroll
                    for (int k = 0; k < 16; k++) {
                        const float wv = wr[k];
                        s0 = fmaf(zv0[k], wv, s0);
                        s1 = fmaf(zv1[k], wv, s1);
                    }
                    const uint32_t zo = (uint32_t)(np * 4) ^ zxm;
                    sts32(zpA + zo, s0);
                    sts32(zpB + zo, s1);
                }
            }
        }
    }
    __syncthreads();   // zp visible; staging reads done before h tiles reused

    // ======== recurrence: 2-phase pipelined schedule, 2 barriers/t ========
    float cs0[8], cs1[8];
    #pragma unroll
    for (int i = 0; i < 8; i++) { cs0[i] = 0.0f; cs1[i] = 0.0f; }

    // bootstrap: layer-0 gates(0) = zp (h0(-1) = 0)
    {
        float D0[32];
        #pragma unroll
        for (int p = 0; p < 4; p++)
            #pragma unroll
            for (int q = 0; q < 2; q++) {
                const uint32_t zo = (uint32_t)((ng * 64 + p * 16 + q * 8 + tig * 2) * 4) ^ zxm;
                const float2 a = lds64(zpA + zo);
                const float2 b = lds64(zpB + zo);
                const int di = p * 8 + q * 4;
                D0[di] = a.x; D0[di + 1] = a.y; D0[di + 2] = b.x; D0[di + 3] = b.y;
            }
        epilogue<0>(D0, cs0, odd, jconst, eH0, exm, sBias1, sFcw);
    }
    bar_grp(bid);    // h0(0) visible

    #pragma unroll 1
    for (int t = 0; t < T; t++) {
        // ---------- GEMM phase ----------
        float D1[32];
        #pragma unroll
        for (int i = 0; i < 32; i++) D1[i] = 0.0f;
        gemm1acc(D1, aH0, bW1I, akl, axm, bkl, bxm);          // h0(t) @ Wih1
        if (t > 0) gemm1acc(D1, aH1, bW1H, akl, axm, bkl, bxm);  // h1(t-1) @ Whh1

        float D0[32];
        if (t < T - 1) {
            #pragma unroll
            for (int p = 0; p < 4; p++)
                #pragma unroll
                for (int q = 0; q < 2; q++) {
                    const uint32_t zo = (uint32_t)((ng * 64 + p * 16 + q * 8 + tig * 2) * 4) ^ zxm;
                    const float2 a = lds64(zpA + zo);
                    const float2 b = lds64(zpB + zo);
                    const int di = p * 8 + q * 4;
                    D0[di] = a.x; D0[di + 1] = a.y; D0[di + 2] = b.x; D0[di + 3] = b.y;
                }
            gemm1acc(D0, aH0, bW0, akl, axm, bkl, bxm);       // h0(t) @ Whh0
        }
        // out(t-1) while GEMMs stream
        if (t > 0) {
            const int gtid = tid & 127;
            if (gtid < 16) {
                const int row = grp * 16 + gtid;
                out[(size_t)(gbase + row) * T + (t - 1)] =
                    sRed[row * 4] + sRed[row * 4 + 1] + sRed[row * 4 + 2] + sRed[row * 4 + 3] + bfc_v;
            }
        }
        bar_grp(bid);    // gemm reads of h0(t), h1(t-1), sRed(t-1) done

        // ---------- MUFU phase: epi1(t) + epi0(t+1) ----------
        float fcacc = epilogue<1>(D1, cs1, odd, jconst, eH1, exm, sBias1, sFcw);
        fcacc += __shfl_xor_sync(0xffffffffu, fcacc, 2);
        if (tig == 0)      sRed[(grp * 16 + gid) * 4 + ng]     = fcacc;
        else if (tig == 1) sRed[(grp * 16 + gid + 8) * 4 + ng] = fcacc;
        if (t < T - 1)
            epilogue<0>(D0, cs0, odd, jconst, eH0, exm, sBias1, sFcw);
        bar_grp(bid);    // h1(t), h0(t+1), sRed(t) visible
    }

    // final output (t = T-1)
    {
        const int gtid = tid & 127;
        if (gtid < 16) {
            const int row = grp * 16 + gtid;
            out[(size_t)(gbase + row) * T + (T - 1)] =
                sRed[row * 4] + sRed[row * 4 + 1] + sRed[row * 4 + 2] + sRed[row * 4 + 3] + bfc_v;
        }
    }
}

// ===========================================================================
extern "C" void kernel_launch(void* const* d_in, const int* in_sizes, int n_in,
                              void* d_out, int out_size)
{
    const float* z    = (const float*)d_in[0];
    const float* Wih0 = (const float*)d_in[1];
    const float* Whh0 = (const float*)d_in[2];
    const float* bih0 = (const float*)d_in[3];
    const float* bhh0 = (const float*)d_in[4];
    const float* Wih1 = (const float*)d_in[5];
    const float* Whh1 = (const float*)d_in[6];
    const float* bih1 = (const float*)d_in[7];
    const float* bhh1 = (const float*)d_in[8];
    const float* Wfc  = (const float*)d_in[9];
    const float* bfc  = (const float*)d_in[10];
    float* out = (float*)d_out;

    const int B = in_sizes[0] / 16;      // 65536

    cudaFuncSetAttribute(lstm_hmma_kernel,
                         cudaFuncAttributeMaxDynamicSharedMemorySize, SMEM_TOTAL);
    lstm_hmma_kernel<<<B / MR, NT, SMEM_TOTAL>>>(
        z, Wih0, Whh0, bih0, bhh0, Wih1, Whh1, bih1, bhh1, Wfc, bfc, out);
}

// round 14
// speedup vs baseline: 1.0169x; 1.0169x over previous
#include <cuda_runtime.h>
#include <cuda_fp16.h>
#include <cstdint>

#define DI __device__ __forceinline__

constexpr int T  = 15;
constexpr int NT = 512;      // 16 warps: 2 groups x 8 warps
constexpr int MR = 64;       // batch rows per CTA (32 per group)

// ---------------- SMEM byte offsets ----------------
// Weight tiles: [256 n'][64 k] fp16, 128B rows, SW128 xor swizzle (32768 B each)
constexpr int O_W0   = 0;         // Whh0 (fp16)
constexpr int O_W1I  = 32768;     // Wih1
constexpr int O_W1H  = 65536;     // Whh1
// h-state tiles: [64 rows][64 k] fp16 SW128 (8192 B each)
constexpr int O_H0   = 98304;
constexpr int O_H1   = 106496;
constexpr int O_BIAS1 = 114688;   // 64 x float4 (i,f,g,o)
constexpr int O_FCW   = 115712;   // 64 floats
constexpr int O_SRED  = 115968;   // 64 rows x 8 floats (2KB)
constexpr int SMEM_TOTAL = 118016;

DI uint32_t smem_u32(const void* p) {
    uint32_t a;
    asm("{ .reg .u64 t; cvta.to.shared.u64 t, %1; cvt.u32.u64 %0, t; }" : "=r"(a) : "l"(p));
    return a;
}
DI void sts16(uint32_t addr, unsigned short u) {
    asm volatile("st.shared.b16 [%0], %1;" :: "r"(addr), "h"(u) : "memory");
}
DI void ldsm4(uint32_t* r, uint32_t addr) {
    asm volatile("ldmatrix.sync.aligned.m8n8.x4.shared.b16 {%0,%1,%2,%3}, [%4];"
                 : "=r"(r[0]), "=r"(r[1]), "=r"(r[2]), "=r"(r[3]) : "r"(addr));
}
DI void mma4(float* d, const uint32_t* a, uint32_t b0, uint32_t b1, const float* c) {
    asm("mma.sync.aligned.m16n8k16.row.col.f32.f16.f16.f32 "
        "{%0,%1,%2,%3},{%4,%5,%6,%7},{%8,%9},{%10,%11,%12,%13};"
        : "=f"(d[0]), "=f"(d[1]), "=f"(d[2]), "=f"(d[3])
        : "r"(a[0]), "r"(a[1]), "r"(a[2]), "r"(a[3]), "r"(b0), "r"(b1),
          "f"(c[0]), "f"(c[1]), "f"(c[2]), "f"(c[3]));
}
// named barrier: per-group sync (256 threads), with memory ordering
DI void bar_grp(int id) {
    asm volatile("bar.sync %0, 256;" :: "r"(id) : "memory");
}

// swizzled offset inside a [n'][64k] fp16 tile with 128B rows
DI uint32_t swoff(int np, int k) {
    return (uint32_t)(np * 128 + k * 2) ^ (uint32_t)((np & 7) << 4);
}

// ---- fast activations: single MUFU.TANH each ----
DI float tanh_(float x) {
    float r;
    asm("tanh.approx.f32 %0, %1;" : "=f"(r) : "f"(x));
    return r;
}
DI float sigf(float x) {                 // 0.5*tanh(x/2) + 0.5
    return fmaf(tanh_(0.5f * x), 0.5f, 0.5f);
}

// 32x32 warp-tile fp16 GEMM, accumulate into D[32]:
// D += A(32 rows) * W(32 n') over K=64.  2 A-frags + 2 B-frags per ks step.
DI void gemm32(float* D, uint32_t aH, uint32_t bW,
               uint32_t akl, uint32_t axm, uint32_t bkl, uint32_t bxm)
{
    #pragma unroll
    for (int ks = 0; ks < 4; ks++) {
        const uint32_t kA = ((uint32_t)(ks * 32) + akl) ^ axm;
        const uint32_t kB = ((uint32_t)(ks * 32) + bkl) ^ bxm;
        uint32_t a0[4], a1[4], b0[4], b1[4];
        ldsm4(a0, aH + kA);
        ldsm4(a1, aH + 2048 + kA);        // +16 rows
        ldsm4(b0, bW + kB);
        ldsm4(b1, bW + 2048 + kB);        // +16 n'
        mma4(D + 0,  a0, b0[0], b0[1], D + 0);
        mma4(D + 4,  a0, b0[2], b0[3], D + 4);
        mma4(D + 8,  a0, b1[0], b1[1], D + 8);
        mma4(D + 12, a0, b1[2], b1[3], D + 12);
        mma4(D + 16, a1, b0[0], b0[1], D + 16);
        mma4(D + 20, a1, b0[2], b0[3], D + 20);
        mma4(D + 24, a1, b1[0], b1[1], D + 24);
        mma4(D + 28, a1, b1[2], b1[3], D + 28);
    }
}

// epilogue: gate exchange, LSTM cell update, h writeback (fp16). LAYER 1 adds
// bias (layer-0 bias folded into zp) and accumulates per-afrag fc dots.
template<int LAYER>
DI void epilogue(float* D, float* cs, int odd, int jconst,
                 uint32_t eH, uint32_t exm,
                 const float4* sBias1, const float* sFcw, float* fcout)
{
    #pragma unroll
    for (int af = 0; af < 2; af++) {
        float fcacc = 0.0f;
        #pragma unroll
        for (int pb = 0; pb < 2; pb++) {
            #pragma unroll
            for (int hf = 0; hf < 2; hf++) {
                const int di = af * 16 + pb * 8 + hf * 4;
                float x0 = D[di], x1 = D[di + 1], x2 = D[di + 2], x3 = D[di + 3];
                float e1 = __shfl_xor_sync(0xffffffffu, odd ? x0 : x2, 1);
                float e2 = __shfl_xor_sync(0xffffffffu, odd ? x1 : x3, 1);
                float gi = odd ? e1 : x0;
                float gf = odd ? e2 : x1;
                float gg = odd ? x2 : e1;
                float go = odd ? x3 : e2;
                const int j = jconst + pb * 4 + hf * 2;
                if (LAYER == 1) {
                    const float4 b = sBias1[j];
                    gi += b.x; gf += b.y; gg += b.z; go += b.w;
                }
                const float i_ = sigf(gi);
                const float f_ = sigf(gf);
                const float g_ = tanh_(gg);
                const float o_ = sigf(go);
                const int ci = af * 4 + pb * 2 + hf;
                const float cn = fmaf(f_, cs[ci], i_ * g_);
                cs[ci] = cn;
                const float h = o_ * tanh_(cn);
                if (LAYER == 1) fcacc = fmaf(h, sFcw[j], fcacc);
                const uint32_t co = ((uint32_t)(j * 2)) ^ exm;
                sts16(eH + (uint32_t)(af * 2048) + co, __half_as_ushort(__float2half_rn(h)));
            }
        }
        if (LAYER == 1) fcout[af] = fcacc;
    }
}

// ===========================================================================
__global__ void __launch_bounds__(NT, 1) lstm_hmma_kernel(
    const float* __restrict__ z,
    const float* __restrict__ Wih0, const float* __restrict__ Whh0,
    const float* __restrict__ bih0, const float* __restrict__ bhh0,
    const float* __restrict__ Wih1, const float* __restrict__ Whh1,
    const float* __restrict__ bih1, const float* __restrict__ bhh1,
    const float* __restrict__ Wfc,  const float* __restrict__ bfc,
    float* __restrict__ out)
{
    extern __shared__ char sm[];
    const uint32_t smb = smem_u32(sm);
    const int tid  = threadIdx.x;
    const int lane = tid & 31;
    const int w    = tid >> 5;
    const int grp  = w >> 3;       // row group: rows grp*32 .. +31
    const int ng   = w & 7;        // n-slice: n' in [ng*32, ng*32+32)
    const int bid  = grp + 1;      // named barrier id

    // ---- ldmatrix lane addressing constants ----
    const int j8  = lane & 7;
    const int sel = lane >> 3;
    const int arow = grp * 32 + j8 + (sel & 1) * 8;     // local A row (frag 0)
    const uint32_t axm = (uint32_t)j8 << 4;             // arow & 7 == j8
    const uint32_t akl = (uint32_t)(sel >> 1) << 4;
    const int bnl = (sel >> 1) * 8 + j8;                // B row within 16-row chunk
    const uint32_t bxm = (uint32_t)j8 << 4;
    const uint32_t bkl = (uint32_t)(sel & 1) << 4;

    const uint32_t aOff = (uint32_t)arow * 128;
    const uint32_t bOff = (uint32_t)(ng * 32 + bnl) * 128;
    const uint32_t aH0 = smb + O_H0 + aOff;
    const uint32_t aH1 = smb + O_H1 + aOff;
    const uint32_t bW0  = smb + O_W0 + bOff;
    const uint32_t bW1I = smb + O_W1I + bOff;
    const uint32_t bW1H = smb + O_W1H + bOff;

    // ---- epilogue lane constants ----
    const int gid = lane >> 2, tig = lane & 3;
    const int odd = tig & 1;
    const int erow = grp * 32 + gid + 8 * odd;          // local row (afrag 0)
    const uint32_t eOff = (uint32_t)erow * 128;
    const uint32_t exm  = (uint32_t)(erow & 7) << 4;
    const uint32_t eH0 = smb + O_H0 + eOff;
    const uint32_t eH1 = smb + O_H1 + eOff;
    const int jconst = ng * 8 + (tig >> 1);

    float4* sBias1 = (float4*)(sm + O_BIAS1);
    float*  sFcw   = (float*)(sm + O_FCW);
    float*  sRed   = (float*)(sm + O_SRED);

    // ======== init: repack weights (fp16, gate-interleaved n'=4j+g) ========
    for (int idx = tid; idx < 16384; idx += NT) {
        const int r = idx >> 6, k = idx & 63;
        const int g = r >> 6, j = r & 63;
        const uint32_t off = swoff(j * 4 + g, k);
        *(__half*)(sm + O_W0  + off) = __float2half_rn(Whh0[idx]);
        *(__half*)(sm + O_W1I + off) = __float2half_rn(Wih1[idx]);
        *(__half*)(sm + O_W1H + off) = __float2half_rn(Whh1[idx]);
    }
    // stage Wih0 (fp32) in the h-tile area (16KB) + bias0 sums in SRED (1KB)
    float* sWz = (float*)(sm + O_H0);      // [256][16] fp32 (spans H0+H1)
    float* sB0 = (float*)(sm + O_SRED);    // [256]
    for (int idx = tid; idx < 4096; idx += NT) sWz[idx] = Wih0[idx];
    for (int idx = tid; idx < 256;  idx += NT) sB0[idx] = bih0[idx] + bhh0[idx];
    if (tid < 64) {
        sBias1[tid] = make_float4(bih1[tid] + bhh1[tid],
                                  bih1[64 + tid] + bhh1[64 + tid],
                                  bih1[128 + tid] + bhh1[128 + tid],
                                  bih1[192 + tid] + bhh1[192 + tid]);
        sFcw[tid] = Wfc[tid];
    }
    const float bfc_v = __ldg(bfc);
    __syncthreads();

    // ======== one-time exact z-projection + bias0 into zp (D-fragment layout) ====
    const int gbase = blockIdx.x * MR;
    float zp[32];
    #pragma unroll 1
    for (int af = 0; af < 2; af++) {
        float zv0[16], zv1[16];
        const int r0 = gbase + grp * 32 + gid + af * 16;
        #pragma unroll
        for (int k = 0; k < 16; k++) {
            zv0[k] = z[(size_t)r0 * 16 + k];
            zv1[k] = z[(size_t)(r0 + 8) * 16 + k];
        }
        #pragma unroll
        for (int pb = 0; pb < 2; pb++) {
            #pragma unroll
            for (int hf = 0; hf < 2; hf++) {
                #pragma unroll
                for (int e = 0; e < 2; e++) {
                    const int np = ng * 32 + pb * 16 + hf * 8 + tig * 2 + e;
                    const int orig = (np & 3) * 64 + (np >> 2);
                    const float* wr = sWz + orig * 16;
                    float s0 = sB0[orig], s1 = s0;
                    #pragma unroll
                    for (int k = 0; k < 16; k++) {
                        const float wv = wr[k];
                        s0 = fmaf(zv0[k], wv, s0);
                        s1 = fmaf(zv1[k], wv, s1);
                    }
                    zp[af * 16 + pb * 8 + hf * 4 + e]     = s0;
                    zp[af * 16 + pb * 8 + hf * 4 + 2 + e] = s1;
                }
            }
        }
    }
    __syncthreads();   // staging reads done before h tiles get overwritten

    // ======== recurrence (each 32-row group runs independently) ========
    float cs0[8], cs1[8], fcv[2];
    #pragma unroll
    for (int i = 0; i < 8; i++) { cs0[i] = 0.0f; cs1[i] = 0.0f; }

    #pragma unroll 1
    for (int t = 0; t < T; t++) {
        float D[32];

        // ----- layer 0: D = zp (+ h0(t-1)·Whh0) -----
        #pragma unroll
        for (int i = 0; i < 32; i++) D[i] = zp[i];
        if (t > 0) gemm32(D, aH0, bW0, akl, axm, bkl, bxm);
        bar_grp(bid);                                      // h0 reads done
        epilogue<0>(D, cs0, odd, jconst, eH0, exm, sBias1, sFcw, fcv);
        bar_grp(bid);                                      // h0(t) visible

        // ----- layer 1: D = h0(t)·Wih1 (+ h1(t-1)·Whh1) -----
        #pragma unroll
        for (int i = 0; i < 32; i++) D[i] = 0.0f;
        gemm32(D, aH0, bW1I, akl, axm, bkl, bxm);
        if (t > 0) gemm32(D, aH1, bW1H, akl, axm, bkl, bxm);
        bar_grp(bid);                                      // h1 reads done
        epilogue<1>(D, cs1, odd, jconst, eH1, exm, sBias1, sFcw, fcv);

        // fc reduction: combine lanes tig 0&2 / 1&3 (same row, different cells)
        fcv[0] += __shfl_xor_sync(0xffffffffu, fcv[0], 2);
        fcv[1] += __shfl_xor_sync(0xffffffffu, fcv[1], 2);
        if (tig < 2) {
            const int r0 = grp * 32 + gid + 8 * tig;
            sRed[r0 * 8 + ng]        = fcv[0];
            sRed[(r0 + 16) * 8 + ng] = fcv[1];
        }
        bar_grp(bid);                                      // h1(t) + sRed visible
        const int gtid = tid & 255;
        if (gtid < 32) {
            const int row = grp * 32 + gtid;
            const float4 s0 = *(const float4*)(sRed + row * 8);
            const float4 s1 = *(const float4*)(sRed + row * 8 + 4);
            out[(size_t)(gbase + row) * T + t] =
                ((s0.x + s0.y) + (s0.z + s0.w)) + ((s1.x + s1.y) + (s1.z + s1.w)) + bfc_v;
        }
    }
}

// ===========================================================================
extern "C" void kernel_launch(void* const* d_in, const int* in_sizes, int n_in,
                              void* d_out, int out_size)
{
    const float* z    = (const float*)d_in[0];
    const float* Wih0 = (const float*)d_in[1];
    const float* Whh0 = (const float*)d_in[2];
    const float* bih0 = (const float*)d_in[3];
    const float* bhh0 = (const float*)d_in[4];
    const float* Wih1 = (const float*)d_in[5];
    const float* Whh1 = (const float*)d_in[6];
    const float* bih1 = (const float*)d_in[7];
    const float* bhh1 = (const float*)d_in[8];
    const float* Wfc  = (const float*)d_in[9];
    const float* bfc  = (const float*)d_in[10];
    float* out = (float*)d_out;

    const int B = in_sizes[0] / 16;      // 65536

    cudaFuncSetAttribute(lstm_hmma_kernel,
                         cudaFuncAttributeMaxDynamicSharedMemorySize, SMEM_TOTAL);
    lstm_hmma_kernel<<<B / MR, NT, SMEM_TOTAL>>>(
        z, Wih0, Whh0, bih0, bhh0, Wih1, Whh1, bih1, bhh1, Wfc, bfc, out);
}